// round 1
// baseline (speedup 1.0000x reference)
#include <cuda_runtime.h>
#include <math.h>

// Problem constants (AirMPRNN: N=50000, E=1e6, T=10, H=8)
#define T_FRAMES 10
#define HID 8
#define MAXN 65536

// Scratch (device globals — no allocation in kernel_launch allowed).
// g_nf[n] = 3 float4 rows: (x0,h0,h1,h2) (h3,h4,h5,h6) (h7,x1,-,-)
__device__ float4 g_nf[MAXN * 3];
__device__ float  g_agg[MAXN];

struct EdgeW { const float *w1,*b1,*w2,*b2,*w3,*b3; };
struct NodeW { const float *w1,*b1,*w2,*b2,*ow1,*ob1,*ow2,*ob2; };

__device__ __forceinline__ float sigmoidf_(float s) {
    return 1.0f / (1.0f + expf(-s));
}

// ---------------------------------------------------------------------------
// Init: hidden = 0, nf table for frame 0, agg = 0
// ---------------------------------------------------------------------------
__global__ void init_kernel(const float* __restrict__ x, int N) {
    int n = blockIdx.x * blockDim.x + threadIdx.x;
    if (n >= N) return;
    float x0 = x[(size_t)n * T_FRAMES * 2 + 0];
    float x1 = x[(size_t)n * T_FRAMES * 2 + 1];
    g_nf[n * 3 + 0] = make_float4(x0, 0.f, 0.f, 0.f);
    g_nf[n * 3 + 1] = make_float4(0.f, 0.f, 0.f, 0.f);
    g_nf[n * 3 + 2] = make_float4(0.f, x1, 0.f, 0.f);
    g_agg[n] = 0.f;
}

// ---------------------------------------------------------------------------
// Edge kernel: per edge e: gather feat=[x0,h0..h7] at src, MLP1 (9->32->32->1),
// msg = sigmoid(.)*edge_attr, atomicAdd into agg[dst].
// ---------------------------------------------------------------------------
__global__ void __launch_bounds__(256) edge_kernel(
    const int* __restrict__ ei, const float* __restrict__ ea,
    EdgeW W, int E, int t)
{
    __shared__ float sW1[9 * 32];
    __shared__ float sW2[32 * 32];
    __shared__ float sB1[32], sB2[32], sW3[32];
    __shared__ float sB3;

    for (int i = threadIdx.x; i < 9 * 32; i += blockDim.x)  sW1[i] = W.w1[i];
    for (int i = threadIdx.x; i < 32 * 32; i += blockDim.x) sW2[i] = W.w2[i];
    if (threadIdx.x < 32) {
        sB1[threadIdx.x] = W.b1[threadIdx.x];
        sB2[threadIdx.x] = W.b2[threadIdx.x];
        sW3[threadIdx.x] = W.w3[threadIdx.x];
    }
    if (threadIdx.x == 0) sB3 = W.b3[0];
    __syncthreads();

    int e = blockIdx.x * blockDim.x + threadIdx.x;
    if (e >= E) return;

    // edge_index layout [2, T, E]
    int src = ei[((size_t)0 * T_FRAMES + t) * (size_t)E + e];
    int dst = ei[((size_t)1 * T_FRAMES + t) * (size_t)E + e];

    float4 a  = g_nf[src * 3 + 0];
    float4 b4 = g_nf[src * 3 + 1];
    float4 c4 = g_nf[src * 3 + 2];
    float in[9] = {a.x, a.y, a.z, a.w, b4.x, b4.y, b4.z, b4.w, c4.x};

    float h[32];
#pragma unroll
    for (int j = 0; j < 32; j++) h[j] = sB1[j];
#pragma unroll
    for (int k = 0; k < 9; k++) {
        float v = in[k];
#pragma unroll
        for (int j = 0; j < 32; j++) h[j] = fmaf(v, sW1[k * 32 + j], h[j]);
    }
#pragma unroll
    for (int j = 0; j < 32; j++) h[j] = fmaxf(h[j], 0.f);

    float h2[32];
#pragma unroll
    for (int j = 0; j < 32; j++) h2[j] = sB2[j];
#pragma unroll
    for (int k = 0; k < 32; k++) {
        float v = h[k];
#pragma unroll
        for (int j = 0; j < 32; j++) h2[j] = fmaf(v, sW2[k * 32 + j], h2[j]);
    }

    float s = sB3;
#pragma unroll
    for (int j = 0; j < 32; j++) s = fmaf(fmaxf(h2[j], 0.f), sW3[j], s);

    // edge_attr layout [E, T, 1]
    float msg = sigmoidf_(s) * ea[(size_t)e * T_FRAMES + t];
    atomicAdd(&g_agg[dst], msg);
}

// ---------------------------------------------------------------------------
// Node kernel: per node n: upd_in=[x1,h0..h7,agg], MLP2 (10->32->8), tanh,
// out head (8->16->1, sigmoid), write out[t], rebuild nf for t+1, reset agg.
// ---------------------------------------------------------------------------
__global__ void __launch_bounds__(256) node_kernel(
    const float* __restrict__ x, NodeW W,
    float* __restrict__ out, int N, int t)
{
    __shared__ float sW1[10 * 32];
    __shared__ float sW2[32 * HID];
    __shared__ float sO1[HID * 16];
    __shared__ float sB1[32], sB2[HID], sOB1[16], sO2[16];
    __shared__ float sOB2;

    for (int i = threadIdx.x; i < 10 * 32; i += blockDim.x)   sW1[i] = W.w1[i];
    for (int i = threadIdx.x; i < 32 * HID; i += blockDim.x)  sW2[i] = W.w2[i];
    for (int i = threadIdx.x; i < HID * 16; i += blockDim.x)  sO1[i] = W.ow1[i];
    if (threadIdx.x < 32) sB1[threadIdx.x] = W.b1[threadIdx.x];
    if (threadIdx.x < HID) sB2[threadIdx.x] = W.b2[threadIdx.x];
    if (threadIdx.x < 16) {
        sOB1[threadIdx.x] = W.ob1[threadIdx.x];
        sO2[threadIdx.x]  = W.ow2[threadIdx.x];
    }
    if (threadIdx.x == 0) sOB2 = W.ob2[0];
    __syncthreads();

    int n = blockIdx.x * blockDim.x + threadIdx.x;
    if (n >= N) return;

    float4 a  = g_nf[n * 3 + 0];
    float4 b4 = g_nf[n * 3 + 1];
    float4 c4 = g_nf[n * 3 + 2];
    float aggv = g_agg[n];
    g_agg[n] = 0.f;  // reset for next frame's edge kernel

    // upd_in = [x1, h0..h7, agg]   (AGG_MEAN=0, AGG_VAR=1 -> identity norm)
    float in[10] = {c4.y, a.y, a.z, a.w, b4.x, b4.y, b4.z, b4.w, c4.x, aggv};

    float u[32];
#pragma unroll
    for (int j = 0; j < 32; j++) u[j] = sB1[j];
#pragma unroll
    for (int k = 0; k < 10; k++) {
        float v = in[k];
#pragma unroll
        for (int j = 0; j < 32; j++) u[j] = fmaf(v, sW1[k * 32 + j], u[j]);
    }
#pragma unroll
    for (int j = 0; j < 32; j++) u[j] = fmaxf(u[j], 0.f);

    float hn[HID];
#pragma unroll
    for (int j = 0; j < HID; j++) hn[j] = sB2[j];
#pragma unroll
    for (int k = 0; k < 32; k++) {
        float v = u[k];
#pragma unroll
        for (int j = 0; j < HID; j++) hn[j] = fmaf(v, sW2[k * HID + j], hn[j]);
    }
#pragma unroll
    for (int j = 0; j < HID; j++) hn[j] = tanhf(fmaxf(hn[j], 0.f));

    float o[16];
#pragma unroll
    for (int j = 0; j < 16; j++) o[j] = sOB1[j];
#pragma unroll
    for (int k = 0; k < HID; k++) {
        float v = hn[k];
#pragma unroll
        for (int j = 0; j < 16; j++) o[j] = fmaf(v, sO1[k * 16 + j], o[j]);
    }

    float s = sOB2;
#pragma unroll
    for (int j = 0; j < 16; j++) s = fmaf(fmaxf(o[j], 0.f), sO2[j], s);

    out[(size_t)t * N + n] = sigmoidf_(s);

    if (t + 1 < T_FRAMES) {
        float x0 = x[(size_t)n * T_FRAMES * 2 + (size_t)(t + 1) * 2 + 0];
        float x1 = x[(size_t)n * T_FRAMES * 2 + (size_t)(t + 1) * 2 + 1];
        g_nf[n * 3 + 0] = make_float4(x0, hn[0], hn[1], hn[2]);
        g_nf[n * 3 + 1] = make_float4(hn[3], hn[4], hn[5], hn[6]);
        g_nf[n * 3 + 2] = make_float4(hn[7], x1, 0.f, 0.f);
    }
}

// ---------------------------------------------------------------------------
extern "C" void kernel_launch(void* const* d_in, const int* in_sizes, int n_in,
                              void* d_out, int out_size)
{
    const float* x  = (const float*)d_in[0];
    const int*   ei = (const int*)  d_in[1];
    const float* ea = (const float*)d_in[2];

    EdgeW ew;
    ew.w1 = (const float*)d_in[3];  ew.b1 = (const float*)d_in[4];
    ew.w2 = (const float*)d_in[5];  ew.b2 = (const float*)d_in[6];
    ew.w3 = (const float*)d_in[7];  ew.b3 = (const float*)d_in[8];

    NodeW nw;
    nw.w1  = (const float*)d_in[9];  nw.b1  = (const float*)d_in[10];
    nw.w2  = (const float*)d_in[11]; nw.b2  = (const float*)d_in[12];
    nw.ow1 = (const float*)d_in[13]; nw.ob1 = (const float*)d_in[14];
    nw.ow2 = (const float*)d_in[15]; nw.ob2 = (const float*)d_in[16];

    float* out = (float*)d_out;

    int N = out_size / T_FRAMES;          // 50000
    int E = in_sizes[2] / T_FRAMES;       // 1000000

    int nb = (N + 255) / 256;
    int eb = (E + 255) / 256;

    init_kernel<<<nb, 256>>>(x, N);
    for (int t = 0; t < T_FRAMES; t++) {
        edge_kernel<<<eb, 256>>>(ei, ea, ew, E, t);
        node_kernel<<<nb, 256>>>(x, nw, out, N, t);
    }
}

// round 2
// speedup vs baseline: 1.5870x; 1.5870x over previous
#include <cuda_runtime.h>
#include <math.h>

// Problem constants (AirMPRNN: N=50000, E=1e6, T=10, H=8)
#define T_FRAMES 10
#define HID 8
#define MAXN 65536

// Scratch (device globals).
// g_nf[n] = 3 float4 rows: (x0,h0,h1,h2) (h3,h4,h5,h6) (h7,x1,-,-)
__device__ float4 g_nf[MAXN * 3];
__device__ float  g_agg[MAXN];

struct EdgeW { const float *w1,*b1,*w2,*b2,*w3,*b3; };
struct NodeW { const float *w1,*b1,*w2,*b2,*ow1,*ob1,*ow2,*ob2; };

typedef unsigned long long u64;

__device__ __forceinline__ float sigmoidf_(float s) {
    return 1.0f / (1.0f + expf(-s));
}

// ---- f32x2 packed helpers (FFMA2 only reachable via PTX fma.rn.f32x2) ----
__device__ __forceinline__ u64 pk2(float a, float b) {
    u64 r; asm("mov.b64 %0, {%1, %2};" : "=l"(r) : "f"(a), "f"(b)); return r;
}
__device__ __forceinline__ void upk2(u64 v, float& a, float& b) {
    asm("mov.b64 {%0, %1}, %2;" : "=f"(a), "=f"(b) : "l"(v));
}
__device__ __forceinline__ u64 ffma2(u64 a, u64 b, u64 c) {
    u64 d; asm("fma.rn.f32x2 %0, %1, %2, %3;" : "=l"(d) : "l"(a), "l"(b), "l"(c)); return d;
}
__device__ __forceinline__ u64 relu2(u64 v) {
    float a, b; upk2(v, a, b);
    return pk2(fmaxf(a, 0.f), fmaxf(b, 0.f));
}

// ---------------------------------------------------------------------------
// Init: hidden = 0, nf table for frame 0, agg = 0
// ---------------------------------------------------------------------------
__global__ void init_kernel(const float* __restrict__ x, int N) {
    int n = blockIdx.x * blockDim.x + threadIdx.x;
    if (n >= N) return;
    float x0 = x[(size_t)n * T_FRAMES * 2 + 0];
    float x1 = x[(size_t)n * T_FRAMES * 2 + 1];
    g_nf[n * 3 + 0] = make_float4(x0, 0.f, 0.f, 0.f);
    g_nf[n * 3 + 1] = make_float4(0.f, 0.f, 0.f, 0.f);
    g_nf[n * 3 + 2] = make_float4(0.f, x1, 0.f, 0.f);
    g_agg[n] = 0.f;
}

// ---------------------------------------------------------------------------
// Edge kernel: 2 edges per thread, f32x2-packed MLP1 (9->32->32->1).
// Weights live in shared memory pre-duplicated as (w,w) pairs so one LDS
// yields a packed operand directly.
// ---------------------------------------------------------------------------
__global__ void __launch_bounds__(256) edge_kernel(
    const int* __restrict__ ei, const float* __restrict__ ea,
    EdgeW W, int E, int t)
{
    __shared__ u64 sW1[9 * 32];
    __shared__ u64 sW2[32 * 32];
    __shared__ u64 sB1[32], sB2[32], sW3[32];
    __shared__ u64 sB3;

    for (int i = threadIdx.x; i < 9 * 32; i += blockDim.x) {
        float w = W.w1[i]; sW1[i] = pk2(w, w);
    }
    for (int i = threadIdx.x; i < 32 * 32; i += blockDim.x) {
        float w = W.w2[i]; sW2[i] = pk2(w, w);
    }
    if (threadIdx.x < 32) {
        float b1 = W.b1[threadIdx.x]; sB1[threadIdx.x] = pk2(b1, b1);
        float b2 = W.b2[threadIdx.x]; sB2[threadIdx.x] = pk2(b2, b2);
        float w3 = W.w3[threadIdx.x]; sW3[threadIdx.x] = pk2(w3, w3);
    }
    if (threadIdx.x == 0) { float b3 = W.b3[0]; sB3 = pk2(b3, b3); }
    __syncthreads();

    int gid = blockIdx.x * blockDim.x + threadIdx.x;
    int e0 = gid * 2;
    if (e0 >= E) return;          // E is even; e0+1 < E whenever e0 < E

    // edge_index layout [2, T, E]; e0 even & t*E even -> 8B aligned int2 loads
    const int2* srcp = (const int2*)&ei[((size_t)0 * T_FRAMES + t) * (size_t)E + e0];
    const int2* dstp = (const int2*)&ei[((size_t)1 * T_FRAMES + t) * (size_t)E + e0];
    int2 src = *srcp;
    int2 dst = *dstp;

    float4 a0 = g_nf[src.x * 3 + 0];
    float4 b0 = g_nf[src.x * 3 + 1];
    float4 c0 = g_nf[src.x * 3 + 2];
    float4 a1 = g_nf[src.y * 3 + 0];
    float4 b1 = g_nf[src.y * 3 + 1];
    float4 c1 = g_nf[src.y * 3 + 2];

    u64 in_p[9];
    in_p[0] = pk2(a0.x, a1.x);
    in_p[1] = pk2(a0.y, a1.y);
    in_p[2] = pk2(a0.z, a1.z);
    in_p[3] = pk2(a0.w, a1.w);
    in_p[4] = pk2(b0.x, b1.x);
    in_p[5] = pk2(b0.y, b1.y);
    in_p[6] = pk2(b0.z, b1.z);
    in_p[7] = pk2(b0.w, b1.w);
    in_p[8] = pk2(c0.x, c1.x);

    // ---- layer 1: 9 -> 32 ----
    u64 h[32];
#pragma unroll
    for (int j = 0; j < 32; j++) h[j] = sB1[j];
#pragma unroll
    for (int k = 0; k < 9; k++) {
        u64 v = in_p[k];
#pragma unroll
        for (int j = 0; j < 32; j++) h[j] = ffma2(v, sW1[k * 32 + j], h[j]);
    }
#pragma unroll
    for (int j = 0; j < 32; j++) h[j] = relu2(h[j]);

    // ---- layer 2 (chunked by 8) folded into layer-3 dot product ----
    u64 s = sB3;
#pragma unroll
    for (int jc = 0; jc < 32; jc += 8) {
        u64 acc[8];
#pragma unroll
        for (int j = 0; j < 8; j++) acc[j] = sB2[jc + j];
#pragma unroll
        for (int k = 0; k < 32; k++) {
            u64 v = h[k];
#pragma unroll
            for (int j = 0; j < 8; j++)
                acc[j] = ffma2(v, sW2[k * 32 + jc + j], acc[j]);
        }
#pragma unroll
        for (int j = 0; j < 8; j++)
            s = ffma2(relu2(acc[j]), sW3[jc + j], s);
    }

    float s0, s1;
    upk2(s, s0, s1);

    // edge_attr layout [E, T, 1]
    float m0 = sigmoidf_(s0) * ea[(size_t)e0 * T_FRAMES + t];
    float m1 = sigmoidf_(s1) * ea[(size_t)(e0 + 1) * T_FRAMES + t];
    atomicAdd(&g_agg[dst.x], m0);
    atomicAdd(&g_agg[dst.y], m1);
}

// ---------------------------------------------------------------------------
// Node kernel: per node n: upd_in=[x1,h0..h7,agg], MLP2 (10->32->8), tanh,
// out head (8->16->1, sigmoid), write out[t], rebuild nf for t+1, reset agg.
// ---------------------------------------------------------------------------
__global__ void __launch_bounds__(256) node_kernel(
    const float* __restrict__ x, NodeW W,
    float* __restrict__ out, int N, int t)
{
    __shared__ float sW1[10 * 32];
    __shared__ float sW2[32 * HID];
    __shared__ float sO1[HID * 16];
    __shared__ float sB1[32], sB2[HID], sOB1[16], sO2[16];
    __shared__ float sOB2;

    for (int i = threadIdx.x; i < 10 * 32; i += blockDim.x)   sW1[i] = W.w1[i];
    for (int i = threadIdx.x; i < 32 * HID; i += blockDim.x)  sW2[i] = W.w2[i];
    for (int i = threadIdx.x; i < HID * 16; i += blockDim.x)  sO1[i] = W.ow1[i];
    if (threadIdx.x < 32) sB1[threadIdx.x] = W.b1[threadIdx.x];
    if (threadIdx.x < HID) sB2[threadIdx.x] = W.b2[threadIdx.x];
    if (threadIdx.x < 16) {
        sOB1[threadIdx.x] = W.ob1[threadIdx.x];
        sO2[threadIdx.x]  = W.ow2[threadIdx.x];
    }
    if (threadIdx.x == 0) sOB2 = W.ob2[0];
    __syncthreads();

    int n = blockIdx.x * blockDim.x + threadIdx.x;
    if (n >= N) return;

    float4 a  = g_nf[n * 3 + 0];
    float4 b4 = g_nf[n * 3 + 1];
    float4 c4 = g_nf[n * 3 + 2];
    float aggv = g_agg[n];
    g_agg[n] = 0.f;  // reset for next frame's edge kernel

    // upd_in = [x1, h0..h7, agg]   (AGG_MEAN=0, AGG_VAR=1 -> identity norm)
    float in[10] = {c4.y, a.y, a.z, a.w, b4.x, b4.y, b4.z, b4.w, c4.x, aggv};

    float u[32];
#pragma unroll
    for (int j = 0; j < 32; j++) u[j] = sB1[j];
#pragma unroll
    for (int k = 0; k < 10; k++) {
        float v = in[k];
#pragma unroll
        for (int j = 0; j < 32; j++) u[j] = fmaf(v, sW1[k * 32 + j], u[j]);
    }
#pragma unroll
    for (int j = 0; j < 32; j++) u[j] = fmaxf(u[j], 0.f);

    float hn[HID];
#pragma unroll
    for (int j = 0; j < HID; j++) hn[j] = sB2[j];
#pragma unroll
    for (int k = 0; k < 32; k++) {
        float v = u[k];
#pragma unroll
        for (int j = 0; j < HID; j++) hn[j] = fmaf(v, sW2[k * HID + j], hn[j]);
    }
#pragma unroll
    for (int j = 0; j < HID; j++) hn[j] = tanhf(fmaxf(hn[j], 0.f));

    float o[16];
#pragma unroll
    for (int j = 0; j < 16; j++) o[j] = sOB1[j];
#pragma unroll
    for (int k = 0; k < HID; k++) {
        float v = hn[k];
#pragma unroll
        for (int j = 0; j < 16; j++) o[j] = fmaf(v, sO1[k * 16 + j], o[j]);
    }

    float s = sOB2;
#pragma unroll
    for (int j = 0; j < 16; j++) s = fmaf(fmaxf(o[j], 0.f), sO2[j], s);

    out[(size_t)t * N + n] = sigmoidf_(s);

    if (t + 1 < T_FRAMES) {
        float x0 = x[(size_t)n * T_FRAMES * 2 + (size_t)(t + 1) * 2 + 0];
        float x1 = x[(size_t)n * T_FRAMES * 2 + (size_t)(t + 1) * 2 + 1];
        g_nf[n * 3 + 0] = make_float4(x0, hn[0], hn[1], hn[2]);
        g_nf[n * 3 + 1] = make_float4(hn[3], hn[4], hn[5], hn[6]);
        g_nf[n * 3 + 2] = make_float4(hn[7], x1, 0.f, 0.f);
    }
}

// ---------------------------------------------------------------------------
extern "C" void kernel_launch(void* const* d_in, const int* in_sizes, int n_in,
                              void* d_out, int out_size)
{
    const float* x  = (const float*)d_in[0];
    const int*   ei = (const int*)  d_in[1];
    const float* ea = (const float*)d_in[2];

    EdgeW ew;
    ew.w1 = (const float*)d_in[3];  ew.b1 = (const float*)d_in[4];
    ew.w2 = (const float*)d_in[5];  ew.b2 = (const float*)d_in[6];
    ew.w3 = (const float*)d_in[7];  ew.b3 = (const float*)d_in[8];

    NodeW nw;
    nw.w1  = (const float*)d_in[9];  nw.b1  = (const float*)d_in[10];
    nw.w2  = (const float*)d_in[11]; nw.b2  = (const float*)d_in[12];
    nw.ow1 = (const float*)d_in[13]; nw.ob1 = (const float*)d_in[14];
    nw.ow2 = (const float*)d_in[15]; nw.ob2 = (const float*)d_in[16];

    float* out = (float*)d_out;

    int N = out_size / T_FRAMES;          // 50000
    int E = in_sizes[2] / T_FRAMES;       // 1000000

    int nb = (N + 255) / 256;
    int eb = ((E / 2) + 255) / 256;

    init_kernel<<<nb, 256>>>(x, N);
    for (int t = 0; t < T_FRAMES; t++) {
        edge_kernel<<<eb, 256>>>(ei, ea, ew, E, t);
        node_kernel<<<nb, 256>>>(x, nw, out, N, t);
    }
}

// round 5
// speedup vs baseline: 4.1920x; 2.6414x over previous
#include <cuda_runtime.h>
#include <math.h>

// Problem constants (AirMPRNN: N=50000, E=1e6, T=10, H=8)
#define T_FRAMES 10
#define HID 8
#define MAXN 65536

// Scratch (device globals).
__device__ float4 g_h[MAXN * 2];   // hidden: (h0..h3),(h4..h7)
__device__ float  g_v[MAXN];       // per-node edge-message scalar for current frame
__device__ float  g_agg[MAXN];     // scatter accumulator

struct EdgeW { const float *w1,*b1,*w2,*b2,*w3,*b3; };
struct NodeW { const float *w1,*b1,*w2,*b2,*ow1,*ob1,*ow2,*ob2; };

typedef unsigned long long u64;

__device__ __forceinline__ float sigmoidf_(float s) {
    return 1.0f / (1.0f + expf(-s));
}

// ---- f32x2 packed helpers ----
__device__ __forceinline__ u64 pk2(float a, float b) {
    u64 r; asm("mov.b64 %0, {%1, %2};" : "=l"(r) : "f"(a), "f"(b)); return r;
}
__device__ __forceinline__ void upk2(u64 v, float& a, float& b) {
    asm("mov.b64 {%0, %1}, %2;" : "=f"(a), "=f"(b) : "l"(v));
}
__device__ __forceinline__ u64 ffma2(u64 a, u64 b, u64 c) {
    u64 d; asm("fma.rn.f32x2 %0, %1, %2, %3;" : "=l"(d) : "l"(a), "l"(b), "l"(c)); return d;
}
__device__ __forceinline__ u64 relu2(u64 v) {
    float a, b; upk2(v, a, b);
    return pk2(fmaxf(a, 0.f), fmaxf(b, 0.f));
}

// ---------------------------------------------------------------------------
// MLP1 (edge MLP, 9->32->32->1 + sigmoid), packed along output channels.
// Weight arrays are viewed as u64 pairs: contiguous j-pairs, no duplication.
// ---------------------------------------------------------------------------
__device__ __forceinline__ float mlp1_eval(
    const float* in9,
    const u64* sW1p, const u64* sB1p,
    const u64* sW2p, const u64* sB2p,
    const u64* sW3p, float b3)
{
    u64 h[16];
#pragma unroll
    for (int j = 0; j < 16; j++) h[j] = sB1p[j];
#pragma unroll
    for (int k = 0; k < 9; k++) {
        u64 v = pk2(in9[k], in9[k]);
#pragma unroll
        for (int j = 0; j < 16; j++) h[j] = ffma2(v, sW1p[k * 16 + j], h[j]);
    }
#pragma unroll
    for (int j = 0; j < 16; j++) h[j] = relu2(h[j]);

    u64 acc[16];
#pragma unroll
    for (int j = 0; j < 16; j++) acc[j] = sB2p[j];
#pragma unroll
    for (int kp = 0; kp < 16; kp++) {
        float ha, hb; upk2(h[kp], ha, hb);
        u64 va = pk2(ha, ha), vb = pk2(hb, hb);
#pragma unroll
        for (int j = 0; j < 16; j++)
            acc[j] = ffma2(va, sW2p[(2 * kp) * 16 + j], acc[j]);
#pragma unroll
        for (int j = 0; j < 16; j++)
            acc[j] = ffma2(vb, sW2p[(2 * kp + 1) * 16 + j], acc[j]);
    }

    u64 s = pk2(0.f, 0.f);
#pragma unroll
    for (int j = 0; j < 16; j++) s = ffma2(relu2(acc[j]), sW3p[j], s);
    float s0, s1; upk2(s, s0, s1);
    return sigmoidf_(s0 + s1 + b3);
}

// ---------------------------------------------------------------------------
// Init: hidden = 0, agg = 0, v0 = sigmoid(MLP1([x0(t=0), 0..0]))
// ---------------------------------------------------------------------------
__global__ void __launch_bounds__(256) init_kernel(
    const float* __restrict__ x, EdgeW W, int N)
{
    __shared__ u64 sW1[9 * 16], sB1[16], sW2[32 * 16], sB2[16], sW3[16];
    float* fW1 = (float*)sW1; float* fB1 = (float*)sB1;
    float* fW2 = (float*)sW2; float* fB2 = (float*)sB2;
    float* fW3 = (float*)sW3;
    for (int i = threadIdx.x; i < 9 * 32; i += blockDim.x)  fW1[i] = W.w1[i];
    for (int i = threadIdx.x; i < 32 * 32; i += blockDim.x) fW2[i] = W.w2[i];
    if (threadIdx.x < 32) {
        fB1[threadIdx.x] = W.b1[threadIdx.x];
        fB2[threadIdx.x] = W.b2[threadIdx.x];
        fW3[threadIdx.x] = W.w3[threadIdx.x];
    }
    __syncthreads();

    int n = blockIdx.x * blockDim.x + threadIdx.x;
    if (n >= N) return;

    float x0 = x[(size_t)n * T_FRAMES * 2 + 0];
    float in9[9] = {x0, 0.f, 0.f, 0.f, 0.f, 0.f, 0.f, 0.f, 0.f};
    g_v[n] = mlp1_eval(in9, sW1, sB1, sW2, sB2, sW3, W.b3[0]);

    g_h[n * 2 + 0] = make_float4(0.f, 0.f, 0.f, 0.f);
    g_h[n * 2 + 1] = make_float4(0.f, 0.f, 0.f, 0.f);
    g_agg[n] = 0.f;
}

// ---------------------------------------------------------------------------
// Edge scatter: msg = v[src] * ea[e]; atomicAdd agg[dst]. 4 edges/thread.
// ---------------------------------------------------------------------------
__global__ void __launch_bounds__(256) edge_kernel(
    const int* __restrict__ ei, const float* __restrict__ ea, int E, int t)
{
    int i = blockIdx.x * blockDim.x + threadIdx.x;
    int e0 = i * 4;
    if (e0 + 3 < E) {
        const int4 src = *(const int4*)&ei[((size_t)0 * T_FRAMES + t) * (size_t)E + e0];
        const int4 dst = *(const int4*)&ei[((size_t)1 * T_FRAMES + t) * (size_t)E + e0];
        float v0 = __ldg(&g_v[src.x]);
        float v1 = __ldg(&g_v[src.y]);
        float v2 = __ldg(&g_v[src.z]);
        float v3 = __ldg(&g_v[src.w]);
        float a0 = ea[(size_t)(e0 + 0) * T_FRAMES + t];
        float a1 = ea[(size_t)(e0 + 1) * T_FRAMES + t];
        float a2 = ea[(size_t)(e0 + 2) * T_FRAMES + t];
        float a3 = ea[(size_t)(e0 + 3) * T_FRAMES + t];
        atomicAdd(&g_agg[dst.x], v0 * a0);
        atomicAdd(&g_agg[dst.y], v1 * a1);
        atomicAdd(&g_agg[dst.z], v2 * a2);
        atomicAdd(&g_agg[dst.w], v3 * a3);
    } else {
        for (int e = e0; e < E; e++) {
            int src = ei[((size_t)0 * T_FRAMES + t) * (size_t)E + e];
            int dst = ei[((size_t)1 * T_FRAMES + t) * (size_t)E + e];
            atomicAdd(&g_agg[dst], __ldg(&g_v[src]) * ea[(size_t)e * T_FRAMES + t]);
        }
    }
}

// ---------------------------------------------------------------------------
// Node kernel (frame t): MLP2 + tanh + output head; writes out[t];
// then computes v for frame t+1 via MLP1([x0(t+1), h_new]); resets agg.
// ---------------------------------------------------------------------------
__global__ void __launch_bounds__(256) node_kernel(
    const float* __restrict__ x, NodeW W, EdgeW EW,
    float* __restrict__ out, int N, int t)
{
    // node weights (packed-j views)
    __shared__ u64 sW1[10 * 16], sB1[16], sW2[32 * 4], sB2[4];
    __shared__ u64 sO1[8 * 8], sOB1[8], sO2[8];
    // edge weights for next-frame v
    __shared__ u64 eW1[9 * 16], eB1[16], eW2[32 * 16], eB2[16], eW3[16];
    __shared__ float sOB2, eB3;

    {
        float* f;
        f = (float*)sW1; for (int i = threadIdx.x; i < 10 * 32; i += blockDim.x) f[i] = W.w1[i];
        f = (float*)sW2; for (int i = threadIdx.x; i < 32 * 8;  i += blockDim.x) f[i] = W.w2[i];
        f = (float*)sO1; for (int i = threadIdx.x; i < 8 * 16;  i += blockDim.x) f[i] = W.ow1[i];
        f = (float*)eW1; for (int i = threadIdx.x; i < 9 * 32;  i += blockDim.x) f[i] = EW.w1[i];
        f = (float*)eW2; for (int i = threadIdx.x; i < 32 * 32; i += blockDim.x) f[i] = EW.w2[i];
        if (threadIdx.x < 32) {
            ((float*)sB1)[threadIdx.x] = W.b1[threadIdx.x];
            ((float*)eB1)[threadIdx.x] = EW.b1[threadIdx.x];
            ((float*)eB2)[threadIdx.x] = EW.b2[threadIdx.x];
            ((float*)eW3)[threadIdx.x] = EW.w3[threadIdx.x];
        }
        if (threadIdx.x < 16) {
            ((float*)sOB1)[threadIdx.x] = W.ob1[threadIdx.x];
            ((float*)sO2)[threadIdx.x]  = W.ow2[threadIdx.x];
        }
        if (threadIdx.x < 8) ((float*)sB2)[threadIdx.x] = W.b2[threadIdx.x];
        if (threadIdx.x == 0) { sOB2 = W.ob2[0]; eB3 = EW.b3[0]; }
    }
    __syncthreads();

    int n = blockIdx.x * blockDim.x + threadIdx.x;
    if (n >= N) return;

    float4 ha = g_h[n * 2 + 0];
    float4 hb = g_h[n * 2 + 1];
    float aggv = g_agg[n];
    g_agg[n] = 0.f;  // reset for next frame
    float x1 = x[(size_t)n * T_FRAMES * 2 + (size_t)t * 2 + 1];

    // upd_in = [x1, h0..h7, agg]
    float in10[10] = {x1, ha.x, ha.y, ha.z, ha.w, hb.x, hb.y, hb.z, hb.w, aggv};

    // MLP2 layer1: 10 -> 32 (16 pairs)
    u64 u[16];
#pragma unroll
    for (int j = 0; j < 16; j++) u[j] = sB1[j];
#pragma unroll
    for (int k = 0; k < 10; k++) {
        u64 v = pk2(in10[k], in10[k]);
#pragma unroll
        for (int j = 0; j < 16; j++) u[j] = ffma2(v, sW1[k * 16 + j], u[j]);
    }
#pragma unroll
    for (int j = 0; j < 16; j++) u[j] = relu2(u[j]);

    // MLP2 layer2: 32 -> 8 (4 pairs)
    u64 a2[4];
#pragma unroll
    for (int j = 0; j < 4; j++) a2[j] = sB2[j];
#pragma unroll
    for (int kp = 0; kp < 16; kp++) {
        float va, vb; upk2(u[kp], va, vb);
        u64 pa = pk2(va, va), pb = pk2(vb, vb);
#pragma unroll
        for (int j = 0; j < 4; j++) a2[j] = ffma2(pa, sW2[(2 * kp) * 4 + j], a2[j]);
#pragma unroll
        for (int j = 0; j < 4; j++) a2[j] = ffma2(pb, sW2[(2 * kp + 1) * 4 + j], a2[j]);
    }
    float hn[HID];
#pragma unroll
    for (int j = 0; j < 4; j++) {
        float va, vb; upk2(a2[j], va, vb);
        hn[2 * j + 0] = tanhf(fmaxf(va, 0.f));
        hn[2 * j + 1] = tanhf(fmaxf(vb, 0.f));
    }

    // Output head: 8 -> 16 -> 1, sigmoid
    u64 o[8];
#pragma unroll
    for (int j = 0; j < 8; j++) o[j] = sOB1[j];
#pragma unroll
    for (int k = 0; k < 8; k++) {
        u64 v = pk2(hn[k], hn[k]);
#pragma unroll
        for (int j = 0; j < 8; j++) o[j] = ffma2(v, sO1[k * 8 + j], o[j]);
    }
    u64 sp = pk2(0.f, 0.f);
#pragma unroll
    for (int j = 0; j < 8; j++) sp = ffma2(relu2(o[j]), sO2[j], sp);
    float sa, sb; upk2(sp, sa, sb);
    out[(size_t)t * N + n] = sigmoidf_(sa + sb + sOB2);

    // Persist hidden and compute next frame's v
    g_h[n * 2 + 0] = make_float4(hn[0], hn[1], hn[2], hn[3]);
    g_h[n * 2 + 1] = make_float4(hn[4], hn[5], hn[6], hn[7]);

    if (t + 1 < T_FRAMES) {
        float x0n = x[(size_t)n * T_FRAMES * 2 + (size_t)(t + 1) * 2 + 0];
        float in9[9] = {x0n, hn[0], hn[1], hn[2], hn[3], hn[4], hn[5], hn[6], hn[7]};
        g_v[n] = mlp1_eval(in9, eW1, eB1, eW2, eB2, eW3, eB3);
    }
}

// ---------------------------------------------------------------------------
extern "C" void kernel_launch(void* const* d_in, const int* in_sizes, int n_in,
                              void* d_out, int out_size)
{
    const float* x  = (const float*)d_in[0];
    const int*   ei = (const int*)  d_in[1];
    const float* ea = (const float*)d_in[2];

    EdgeW ew;
    ew.w1 = (const float*)d_in[3];  ew.b1 = (const float*)d_in[4];
    ew.w2 = (const float*)d_in[5];  ew.b2 = (const float*)d_in[6];
    ew.w3 = (const float*)d_in[7];  ew.b3 = (const float*)d_in[8];

    NodeW nw;
    nw.w1  = (const float*)d_in[9];  nw.b1  = (const float*)d_in[10];
    nw.w2  = (const float*)d_in[11]; nw.b2  = (const float*)d_in[12];
    nw.ow1 = (const float*)d_in[13]; nw.ob1 = (const float*)d_in[14];
    nw.ow2 = (const float*)d_in[15]; nw.ob2 = (const float*)d_in[16];

    float* out = (float*)d_out;

    int N = out_size / T_FRAMES;          // 50000
    int E = in_sizes[2] / T_FRAMES;       // 1000000

    int nb = (N + 255) / 256;
    int eb = ((E + 3) / 4 + 255) / 256;

    init_kernel<<<nb, 256>>>(x, ew, N);
    for (int t = 0; t < T_FRAMES; t++) {
        edge_kernel<<<eb, 256>>>(ei, ea, E, t);
        node_kernel<<<nb, 256>>>(x, nw, ew, out, N, t);
    }
}

// round 6
// speedup vs baseline: 6.1467x; 1.4663x over previous
#include <cuda_runtime.h>
#include <math.h>

// Problem constants (AirMPRNN: N=50000, E=1e6, T=10, H=8)
#define T_FRAMES 10
#define HID 8
#define MAXN 65536
#define MAXE 1048576

// Scratch (device globals).
__device__ float4 g_h[MAXN * 2];   // hidden: (h0..h3),(h4..h7)
__device__ float  g_v[MAXN];       // per-node edge-message scalar for current frame
__device__ float  g_agg[MAXN];     // scatter accumulator
__device__ float  g_eaT[(size_t)T_FRAMES * MAXE];  // edge_attr transposed [T][E]

struct EdgeW { const float *w1,*b1,*w2,*b2,*w3,*b3; };
struct NodeW { const float *w1,*b1,*w2,*b2,*ow1,*ob1,*ow2,*ob2; };

typedef unsigned long long u64;

__device__ __forceinline__ float sigmoidf_(float s) {
    // fast sigmoid; |rel err| ~1e-6, far under the 1e-3 gate
    return __fdividef(1.0f, 1.0f + __expf(-s));
}
__device__ __forceinline__ float tanhf_(float s) {
    // tanh(x) = 1 - 2/(exp(2x)+1)
    return 1.0f - __fdividef(2.0f, __expf(2.0f * s) + 1.0f);
}

// ---- f32x2 packed helpers ----
__device__ __forceinline__ u64 pk2(float a, float b) {
    u64 r; asm("mov.b64 %0, {%1, %2};" : "=l"(r) : "f"(a), "f"(b)); return r;
}
__device__ __forceinline__ void upk2(u64 v, float& a, float& b) {
    asm("mov.b64 {%0, %1}, %2;" : "=f"(a), "=f"(b) : "l"(v));
}
__device__ __forceinline__ u64 ffma2(u64 a, u64 b, u64 c) {
    u64 d; asm("fma.rn.f32x2 %0, %1, %2, %3;" : "=l"(d) : "l"(a), "l"(b), "l"(c)); return d;
}
__device__ __forceinline__ u64 relu2(u64 v) {
    float a, b; upk2(v, a, b);
    return pk2(fmaxf(a, 0.f), fmaxf(b, 0.f));
}

// ---------------------------------------------------------------------------
// MLP1 (edge MLP, 9->32->32->1 + sigmoid), packed along output channels.
// ---------------------------------------------------------------------------
__device__ __forceinline__ float mlp1_eval(
    const float* in9,
    const u64* sW1p, const u64* sB1p,
    const u64* sW2p, const u64* sB2p,
    const u64* sW3p, float b3)
{
    u64 h[16];
#pragma unroll
    for (int j = 0; j < 16; j++) h[j] = sB1p[j];
#pragma unroll
    for (int k = 0; k < 9; k++) {
        u64 v = pk2(in9[k], in9[k]);
#pragma unroll
        for (int j = 0; j < 16; j++) h[j] = ffma2(v, sW1p[k * 16 + j], h[j]);
    }
#pragma unroll
    for (int j = 0; j < 16; j++) h[j] = relu2(h[j]);

    u64 acc[16];
#pragma unroll
    for (int j = 0; j < 16; j++) acc[j] = sB2p[j];
#pragma unroll
    for (int kp = 0; kp < 16; kp++) {
        float ha, hb; upk2(h[kp], ha, hb);
        u64 va = pk2(ha, ha), vb = pk2(hb, hb);
#pragma unroll
        for (int j = 0; j < 16; j++)
            acc[j] = ffma2(va, sW2p[(2 * kp) * 16 + j], acc[j]);
#pragma unroll
        for (int j = 0; j < 16; j++)
            acc[j] = ffma2(vb, sW2p[(2 * kp + 1) * 16 + j], acc[j]);
    }

    u64 s = pk2(0.f, 0.f);
#pragma unroll
    for (int j = 0; j < 16; j++) s = ffma2(relu2(acc[j]), sW3p[j], s);
    float s0, s1; upk2(s, s0, s1);
    return sigmoidf_(s0 + s1 + b3);
}

// ---------------------------------------------------------------------------
// ea transpose: [E,T] -> [T][E]. Tile of 256 edges: coalesced 2560-float read
// into smem, then per-t coalesced writes.
// ---------------------------------------------------------------------------
__global__ void __launch_bounds__(256) transpose_ea_kernel(
    const float* __restrict__ ea, int E)
{
    __shared__ float tile[256 * T_FRAMES];
    int base = blockIdx.x * 256;                 // first edge of tile
    int cnt = min(256, E - base);                // edges in this tile
    int nflt = cnt * T_FRAMES;

    for (int i = threadIdx.x; i < nflt; i += 256)
        tile[i] = ea[(size_t)base * T_FRAMES + i];
    __syncthreads();

#pragma unroll
    for (int t = 0; t < T_FRAMES; t++) {
        if (threadIdx.x < cnt)
            g_eaT[(size_t)t * E + base + threadIdx.x] =
                tile[threadIdx.x * T_FRAMES + t];
    }
}

// ---------------------------------------------------------------------------
// Init: hidden = 0, agg = 0, v0 = sigmoid(MLP1([x0(t=0), 0..0]))
// ---------------------------------------------------------------------------
__global__ void __launch_bounds__(256) init_kernel(
    const float* __restrict__ x, EdgeW W, int N)
{
    __shared__ u64 sW1[9 * 16], sB1[16], sW2[32 * 16], sB2[16], sW3[16];
    float* fW1 = (float*)sW1; float* fB1 = (float*)sB1;
    float* fW2 = (float*)sW2; float* fB2 = (float*)sB2;
    float* fW3 = (float*)sW3;
    for (int i = threadIdx.x; i < 9 * 32; i += blockDim.x)  fW1[i] = W.w1[i];
    for (int i = threadIdx.x; i < 32 * 32; i += blockDim.x) fW2[i] = W.w2[i];
    if (threadIdx.x < 32) {
        fB1[threadIdx.x] = W.b1[threadIdx.x];
        fB2[threadIdx.x] = W.b2[threadIdx.x];
        fW3[threadIdx.x] = W.w3[threadIdx.x];
    }
    __syncthreads();

    int n = blockIdx.x * blockDim.x + threadIdx.x;
    if (n >= N) return;

    float x0 = x[(size_t)n * T_FRAMES * 2 + 0];
    float in9[9] = {x0, 0.f, 0.f, 0.f, 0.f, 0.f, 0.f, 0.f, 0.f};
    g_v[n] = mlp1_eval(in9, sW1, sB1, sW2, sB2, sW3, W.b3[0]);

    g_h[n * 2 + 0] = make_float4(0.f, 0.f, 0.f, 0.f);
    g_h[n * 2 + 1] = make_float4(0.f, 0.f, 0.f, 0.f);
    g_agg[n] = 0.f;
}

// ---------------------------------------------------------------------------
// Edge scatter: msg = v[src] * eaT[t][e]; atomicAdd agg[dst]. 4 edges/thread.
// ---------------------------------------------------------------------------
__global__ void __launch_bounds__(256) edge_kernel(
    const int* __restrict__ ei, int E, int t)
{
    int i = blockIdx.x * blockDim.x + threadIdx.x;
    int e0 = i * 4;
    if (e0 + 3 < E) {
        const int4 src = *(const int4*)&ei[((size_t)0 * T_FRAMES + t) * (size_t)E + e0];
        const int4 dst = *(const int4*)&ei[((size_t)1 * T_FRAMES + t) * (size_t)E + e0];
        const float4 av = *(const float4*)&g_eaT[(size_t)t * E + e0];
        float v0 = __ldg(&g_v[src.x]);
        float v1 = __ldg(&g_v[src.y]);
        float v2 = __ldg(&g_v[src.z]);
        float v3 = __ldg(&g_v[src.w]);
        atomicAdd(&g_agg[dst.x], v0 * av.x);
        atomicAdd(&g_agg[dst.y], v1 * av.y);
        atomicAdd(&g_agg[dst.z], v2 * av.z);
        atomicAdd(&g_agg[dst.w], v3 * av.w);
    } else {
        for (int e = e0; e < E; e++) {
            int src = ei[((size_t)0 * T_FRAMES + t) * (size_t)E + e];
            int dst = ei[((size_t)1 * T_FRAMES + t) * (size_t)E + e];
            atomicAdd(&g_agg[dst], __ldg(&g_v[src]) * g_eaT[(size_t)t * E + e]);
        }
    }
}

// ---------------------------------------------------------------------------
// Node kernel (frame t): MLP2 + tanh + output head; writes out[t];
// then computes v for frame t+1 via MLP1([x0(t+1), h_new]); resets agg.
// ---------------------------------------------------------------------------
__global__ void __launch_bounds__(256) node_kernel(
    const float* __restrict__ x, NodeW W, EdgeW EW,
    float* __restrict__ out, int N, int t)
{
    // node weights (packed-j views)
    __shared__ u64 sW1[10 * 16], sB1[16], sW2[32 * 4], sB2[4];
    __shared__ u64 sO1[8 * 8], sOB1[8], sO2[8];
    // edge weights for next-frame v
    __shared__ u64 eW1[9 * 16], eB1[16], eW2[32 * 16], eB2[16], eW3[16];
    __shared__ float sOB2, eB3;

    {
        float* f;
        f = (float*)sW1; for (int i = threadIdx.x; i < 10 * 32; i += blockDim.x) f[i] = W.w1[i];
        f = (float*)sW2; for (int i = threadIdx.x; i < 32 * 8;  i += blockDim.x) f[i] = W.w2[i];
        f = (float*)sO1; for (int i = threadIdx.x; i < 8 * 16;  i += blockDim.x) f[i] = W.ow1[i];
        f = (float*)eW1; for (int i = threadIdx.x; i < 9 * 32;  i += blockDim.x) f[i] = EW.w1[i];
        f = (float*)eW2; for (int i = threadIdx.x; i < 32 * 32; i += blockDim.x) f[i] = EW.w2[i];
        if (threadIdx.x < 32) {
            ((float*)sB1)[threadIdx.x] = W.b1[threadIdx.x];
            ((float*)eB1)[threadIdx.x] = EW.b1[threadIdx.x];
            ((float*)eB2)[threadIdx.x] = EW.b2[threadIdx.x];
            ((float*)eW3)[threadIdx.x] = EW.w3[threadIdx.x];
        }
        if (threadIdx.x < 16) {
            ((float*)sOB1)[threadIdx.x] = W.ob1[threadIdx.x];
            ((float*)sO2)[threadIdx.x]  = W.ow2[threadIdx.x];
        }
        if (threadIdx.x < 8) ((float*)sB2)[threadIdx.x] = W.b2[threadIdx.x];
        if (threadIdx.x == 0) { sOB2 = W.ob2[0]; eB3 = EW.b3[0]; }
    }
    __syncthreads();

    int n = blockIdx.x * blockDim.x + threadIdx.x;
    if (n >= N) return;

    float4 ha = g_h[n * 2 + 0];
    float4 hb = g_h[n * 2 + 1];
    float aggv = g_agg[n];
    g_agg[n] = 0.f;  // reset for next frame
    float x1 = x[(size_t)n * T_FRAMES * 2 + (size_t)t * 2 + 1];

    // upd_in = [x1, h0..h7, agg]
    float in10[10] = {x1, ha.x, ha.y, ha.z, ha.w, hb.x, hb.y, hb.z, hb.w, aggv};

    // MLP2 layer1: 10 -> 32 (16 pairs)
    u64 u[16];
#pragma unroll
    for (int j = 0; j < 16; j++) u[j] = sB1[j];
#pragma unroll
    for (int k = 0; k < 10; k++) {
        u64 v = pk2(in10[k], in10[k]);
#pragma unroll
        for (int j = 0; j < 16; j++) u[j] = ffma2(v, sW1[k * 16 + j], u[j]);
    }
#pragma unroll
    for (int j = 0; j < 16; j++) u[j] = relu2(u[j]);

    // MLP2 layer2: 32 -> 8 (4 pairs)
    u64 a2[4];
#pragma unroll
    for (int j = 0; j < 4; j++) a2[j] = sB2[j];
#pragma unroll
    for (int kp = 0; kp < 16; kp++) {
        float va, vb; upk2(u[kp], va, vb);
        u64 pa = pk2(va, va), pb = pk2(vb, vb);
#pragma unroll
        for (int j = 0; j < 4; j++) a2[j] = ffma2(pa, sW2[(2 * kp) * 4 + j], a2[j]);
#pragma unroll
        for (int j = 0; j < 4; j++) a2[j] = ffma2(pb, sW2[(2 * kp + 1) * 4 + j], a2[j]);
    }
    float hn[HID];
#pragma unroll
    for (int j = 0; j < 4; j++) {
        float va, vb; upk2(a2[j], va, vb);
        hn[2 * j + 0] = tanhf_(fmaxf(va, 0.f));
        hn[2 * j + 1] = tanhf_(fmaxf(vb, 0.f));
    }

    // Output head: 8 -> 16 -> 1, sigmoid
    u64 o[8];
#pragma unroll
    for (int j = 0; j < 8; j++) o[j] = sOB1[j];
#pragma unroll
    for (int k = 0; k < 8; k++) {
        u64 v = pk2(hn[k], hn[k]);
#pragma unroll
        for (int j = 0; j < 8; j++) o[j] = ffma2(v, sO1[k * 8 + j], o[j]);
    }
    u64 sp = pk2(0.f, 0.f);
#pragma unroll
    for (int j = 0; j < 8; j++) sp = ffma2(relu2(o[j]), sO2[j], sp);
    float sa, sb; upk2(sp, sa, sb);
    out[(size_t)t * N + n] = sigmoidf_(sa + sb + sOB2);

    // Persist hidden and compute next frame's v
    g_h[n * 2 + 0] = make_float4(hn[0], hn[1], hn[2], hn[3]);
    g_h[n * 2 + 1] = make_float4(hn[4], hn[5], hn[6], hn[7]);

    if (t + 1 < T_FRAMES) {
        float x0n = x[(size_t)n * T_FRAMES * 2 + (size_t)(t + 1) * 2 + 0];
        float in9[9] = {x0n, hn[0], hn[1], hn[2], hn[3], hn[4], hn[5], hn[6], hn[7]};
        g_v[n] = mlp1_eval(in9, eW1, eB1, eW2, eB2, eW3, eB3);
    }
}

// ---------------------------------------------------------------------------
extern "C" void kernel_launch(void* const* d_in, const int* in_sizes, int n_in,
                              void* d_out, int out_size)
{
    const float* x  = (const float*)d_in[0];
    const int*   ei = (const int*)  d_in[1];
    const float* ea = (const float*)d_in[2];

    EdgeW ew;
    ew.w1 = (const float*)d_in[3];  ew.b1 = (const float*)d_in[4];
    ew.w2 = (const float*)d_in[5];  ew.b2 = (const float*)d_in[6];
    ew.w3 = (const float*)d_in[7];  ew.b3 = (const float*)d_in[8];

    NodeW nw;
    nw.w1  = (const float*)d_in[9];  nw.b1  = (const float*)d_in[10];
    nw.w2  = (const float*)d_in[11]; nw.b2  = (const float*)d_in[12];
    nw.ow1 = (const float*)d_in[13]; nw.ob1 = (const float*)d_in[14];
    nw.ow2 = (const float*)d_in[15]; nw.ob2 = (const float*)d_in[16];

    float* out = (float*)d_out;

    int N = out_size / T_FRAMES;          // 50000
    int E = in_sizes[2] / T_FRAMES;       // 1000000

    int nb = (N + 255) / 256;
    int eb = ((E + 3) / 4 + 255) / 256;
    int tb = (E + 255) / 256;

    transpose_ea_kernel<<<tb, 256>>>(ea, E);
    init_kernel<<<nb, 256>>>(x, ew, N);
    for (int t = 0; t < T_FRAMES; t++) {
        edge_kernel<<<eb, 256>>>(ei, E, t);
        node_kernel<<<nb, 256>>>(x, nw, ew, out, N, t);
    }
}

// round 7
// speedup vs baseline: 6.2013x; 1.0089x over previous
#include <cuda_runtime.h>
#include <math.h>

// Problem constants (AirMPRNN: N=50000, E=1e6, T=10, H=8)
#define T_FRAMES 10
#define HID 8
#define MAXN 65536
#define MAXE 1048576

// Scratch (device globals).
__device__ float4 g_h[MAXN * 2];   // hidden: (h0..h3),(h4..h7)
__device__ float  g_v[MAXN];       // per-node edge-message scalar for current frame
__device__ float  g_agg[MAXN];     // scatter accumulator
__device__ float  g_eaT[(size_t)T_FRAMES * MAXE];  // edge_attr transposed [T][E]

struct EdgeW { const float *w1,*b1,*w2,*b2,*w3,*b3; };
struct NodeW { const float *w1,*b1,*w2,*b2,*ow1,*ob1,*ow2,*ob2; };

typedef unsigned long long u64;

__device__ __forceinline__ float sigmoidf_(float s) {
    return __fdividef(1.0f, 1.0f + __expf(-s));
}
__device__ __forceinline__ float tanhf_(float s) {
    return 1.0f - __fdividef(2.0f, __expf(2.0f * s) + 1.0f);
}

// ---- f32x2 packed helpers ----
__device__ __forceinline__ u64 pk2(float a, float b) {
    u64 r; asm("mov.b64 %0, {%1, %2};" : "=l"(r) : "f"(a), "f"(b)); return r;
}
__device__ __forceinline__ void upk2(u64 v, float& a, float& b) {
    asm("mov.b64 {%0, %1}, %2;" : "=f"(a), "=f"(b) : "l"(v));
}
__device__ __forceinline__ u64 ffma2(u64 a, u64 b, u64 c) {
    u64 d; asm("fma.rn.f32x2 %0, %1, %2, %3;" : "=l"(d) : "l"(a), "l"(b), "l"(c)); return d;
}
__device__ __forceinline__ u64 add2(u64 a, u64 b) {
    u64 d; asm("add.rn.f32x2 %0, %1, %2;" : "=l"(d) : "l"(a), "l"(b)); return d;
}
__device__ __forceinline__ u64 relu2(u64 v) {
    float a, b; upk2(v, a, b);
    return pk2(fmaxf(a, 0.f), fmaxf(b, 0.f));
}
__device__ __forceinline__ u64 shflx1_u64(u64 v) {
    unsigned lo = (unsigned)v, hi = (unsigned)(v >> 32);
    lo = __shfl_xor_sync(0xFFFFFFFFu, lo, 1);
    hi = __shfl_xor_sync(0xFFFFFFFFu, hi, 1);
    return ((u64)hi << 32) | lo;
}

// ---------------------------------------------------------------------------
// Full (single-thread) MLP1 eval — used only by init_kernel.
// ---------------------------------------------------------------------------
__device__ __forceinline__ float mlp1_eval(
    const float* in9,
    const u64* sW1p, const u64* sB1p,
    const u64* sW2p, const u64* sB2p,
    const u64* sW3p, float b3)
{
    u64 h[16];
#pragma unroll
    for (int j = 0; j < 16; j++) h[j] = sB1p[j];
#pragma unroll
    for (int k = 0; k < 9; k++) {
        u64 v = pk2(in9[k], in9[k]);
#pragma unroll
        for (int j = 0; j < 16; j++) h[j] = ffma2(v, sW1p[k * 16 + j], h[j]);
    }
#pragma unroll
    for (int j = 0; j < 16; j++) h[j] = relu2(h[j]);

    u64 acc[16];
#pragma unroll
    for (int j = 0; j < 16; j++) acc[j] = sB2p[j];
#pragma unroll
    for (int kp = 0; kp < 16; kp++) {
        float ha, hb; upk2(h[kp], ha, hb);
        u64 va = pk2(ha, ha), vb = pk2(hb, hb);
#pragma unroll
        for (int j = 0; j < 16; j++)
            acc[j] = ffma2(va, sW2p[(2 * kp) * 16 + j], acc[j]);
#pragma unroll
        for (int j = 0; j < 16; j++)
            acc[j] = ffma2(vb, sW2p[(2 * kp + 1) * 16 + j], acc[j]);
    }

    u64 s = pk2(0.f, 0.f);
#pragma unroll
    for (int j = 0; j < 16; j++) s = ffma2(relu2(acc[j]), sW3p[j], s);
    float s0, s1; upk2(s, s0, s1);
    return sigmoidf_(s0 + s1 + b3);
}

// ---------------------------------------------------------------------------
// ea transpose: [E,T] -> [T][E].
// ---------------------------------------------------------------------------
__global__ void __launch_bounds__(256) transpose_ea_kernel(
    const float* __restrict__ ea, int E)
{
    __shared__ float tile[256 * T_FRAMES];
    int base = blockIdx.x * 256;
    int cnt = min(256, E - base);
    int nflt = cnt * T_FRAMES;

    for (int i = threadIdx.x; i < nflt; i += 256)
        tile[i] = ea[(size_t)base * T_FRAMES + i];
    __syncthreads();

#pragma unroll
    for (int t = 0; t < T_FRAMES; t++) {
        if (threadIdx.x < cnt)
            g_eaT[(size_t)t * E + base + threadIdx.x] =
                tile[threadIdx.x * T_FRAMES + t];
    }
}

// ---------------------------------------------------------------------------
// Init: hidden = 0, agg = 0, v0 = sigmoid(MLP1([x0(t=0), 0..0]))
// ---------------------------------------------------------------------------
__global__ void __launch_bounds__(256) init_kernel(
    const float* __restrict__ x, EdgeW W, int N)
{
    __shared__ u64 sW1[9 * 16], sB1[16], sW2[32 * 16], sB2[16], sW3[16];
    float* fW1 = (float*)sW1; float* fB1 = (float*)sB1;
    float* fW2 = (float*)sW2; float* fB2 = (float*)sB2;
    float* fW3 = (float*)sW3;
    for (int i = threadIdx.x; i < 9 * 32; i += blockDim.x)  fW1[i] = W.w1[i];
    for (int i = threadIdx.x; i < 32 * 32; i += blockDim.x) fW2[i] = W.w2[i];
    if (threadIdx.x < 32) {
        fB1[threadIdx.x] = W.b1[threadIdx.x];
        fB2[threadIdx.x] = W.b2[threadIdx.x];
        fW3[threadIdx.x] = W.w3[threadIdx.x];
    }
    __syncthreads();

    int n = blockIdx.x * blockDim.x + threadIdx.x;
    if (n >= N) return;

    float x0 = x[(size_t)n * T_FRAMES * 2 + 0];
    float in9[9] = {x0, 0.f, 0.f, 0.f, 0.f, 0.f, 0.f, 0.f, 0.f};
    g_v[n] = mlp1_eval(in9, sW1, sB1, sW2, sB2, sW3, W.b3[0]);

    g_h[n * 2 + 0] = make_float4(0.f, 0.f, 0.f, 0.f);
    g_h[n * 2 + 1] = make_float4(0.f, 0.f, 0.f, 0.f);
    g_agg[n] = 0.f;
}

// ---------------------------------------------------------------------------
// Edge scatter: 8 edges/thread. msg = v[src]*eaT[t][e]; atomicAdd agg[dst].
// ---------------------------------------------------------------------------
__global__ void __launch_bounds__(256) edge_kernel(
    const int* __restrict__ ei, int E, int t)
{
    int i = blockIdx.x * blockDim.x + threadIdx.x;
    int e0 = i * 8;
    const int* srcb = &ei[((size_t)0 * T_FRAMES + t) * (size_t)E];
    const int* dstb = &ei[((size_t)1 * T_FRAMES + t) * (size_t)E];
    if (e0 + 7 < E) {
        int4 s0 = *(const int4*)&srcb[e0];
        int4 s1 = *(const int4*)&srcb[e0 + 4];
        int4 d0 = *(const int4*)&dstb[e0];
        int4 d1 = *(const int4*)&dstb[e0 + 4];
        float4 a0 = *(const float4*)&g_eaT[(size_t)t * E + e0];
        float4 a1 = *(const float4*)&g_eaT[(size_t)t * E + e0 + 4];
        float v0 = __ldg(&g_v[s0.x]);
        float v1 = __ldg(&g_v[s0.y]);
        float v2 = __ldg(&g_v[s0.z]);
        float v3 = __ldg(&g_v[s0.w]);
        float v4 = __ldg(&g_v[s1.x]);
        float v5 = __ldg(&g_v[s1.y]);
        float v6 = __ldg(&g_v[s1.z]);
        float v7 = __ldg(&g_v[s1.w]);
        atomicAdd(&g_agg[d0.x], v0 * a0.x);
        atomicAdd(&g_agg[d0.y], v1 * a0.y);
        atomicAdd(&g_agg[d0.z], v2 * a0.z);
        atomicAdd(&g_agg[d0.w], v3 * a0.w);
        atomicAdd(&g_agg[d1.x], v4 * a1.x);
        atomicAdd(&g_agg[d1.y], v5 * a1.y);
        atomicAdd(&g_agg[d1.z], v6 * a1.z);
        atomicAdd(&g_agg[d1.w], v7 * a1.w);
    } else {
        for (int e = e0; e < E; e++) {
            atomicAdd(&g_agg[dstb[e]], __ldg(&g_v[srcb[e]]) * g_eaT[(size_t)t * E + e]);
        }
    }
}

// ---------------------------------------------------------------------------
// Node kernel (frame t): TWO threads per node (lane pair). Lane q owns packed
// output-channel pairs [8q,8q+8) of the 32-wide layers (and [4q,4q+4) of the
// 8-wide/16-wide ones). Cross-lane combines via shfl_xor(1).
// ---------------------------------------------------------------------------
__global__ void __launch_bounds__(256) node_kernel(
    const float* __restrict__ x, NodeW W, EdgeW EW,
    float* __restrict__ out, int N, int t)
{
    // node weights (packed-j views)
    __shared__ u64 sW1[10 * 16], sB1[16], sW2[32 * 4], sB2[4];
    __shared__ u64 sO1[8 * 8], sOB1[8], sO2[8];
    // edge weights for next-frame v
    __shared__ u64 eW1[9 * 16], eB1[16], eW2[32 * 16], eB2[16], eW3[16];
    __shared__ float sOB2, eB3;

    {
        float* f;
        f = (float*)sW1; for (int i = threadIdx.x; i < 10 * 32; i += blockDim.x) f[i] = W.w1[i];
        f = (float*)sW2; for (int i = threadIdx.x; i < 32 * 8;  i += blockDim.x) f[i] = W.w2[i];
        f = (float*)sO1; for (int i = threadIdx.x; i < 8 * 16;  i += blockDim.x) f[i] = W.ow1[i];
        f = (float*)eW1; for (int i = threadIdx.x; i < 9 * 32;  i += blockDim.x) f[i] = EW.w1[i];
        f = (float*)eW2; for (int i = threadIdx.x; i < 32 * 32; i += blockDim.x) f[i] = EW.w2[i];
        if (threadIdx.x < 32) {
            ((float*)sB1)[threadIdx.x] = W.b1[threadIdx.x];
            ((float*)eB1)[threadIdx.x] = EW.b1[threadIdx.x];
            ((float*)eB2)[threadIdx.x] = EW.b2[threadIdx.x];
            ((float*)eW3)[threadIdx.x] = EW.w3[threadIdx.x];
        }
        if (threadIdx.x < 16) {
            ((float*)sOB1)[threadIdx.x] = W.ob1[threadIdx.x];
            ((float*)sO2)[threadIdx.x]  = W.ow2[threadIdx.x];
        }
        if (threadIdx.x < 8) ((float*)sB2)[threadIdx.x] = W.b2[threadIdx.x];
        if (threadIdx.x == 0) { sOB2 = W.ob2[0]; eB3 = EW.b3[0]; }
    }
    __syncthreads();

    int gid = blockIdx.x * blockDim.x + threadIdx.x;
    int n = gid >> 1;
    int q = gid & 1;
    bool valid = (n < N);
    int nc = valid ? n : (N - 1);          // clamp; no early exit (shuffles!)
    int jb = q * 8;                        // packed-pair base for 32-wide layers

    float4 ha = g_h[nc * 2 + 0];
    float4 hb = g_h[nc * 2 + 1];
    float aggv = g_agg[nc];
    if (valid && q == 0) g_agg[n] = 0.f;   // reset for next frame
    float x1 = x[(size_t)nc * T_FRAMES * 2 + (size_t)t * 2 + 1];

    float in10[10] = {x1, ha.x, ha.y, ha.z, ha.w, hb.x, hb.y, hb.z, hb.w, aggv};

    // ---- MLP2 layer1: 10 -> 32, this lane's 8 pairs ----
    u64 u[8];
#pragma unroll
    for (int j = 0; j < 8; j++) u[j] = sB1[jb + j];
#pragma unroll
    for (int k = 0; k < 10; k++) {
        u64 v = pk2(in10[k], in10[k]);
#pragma unroll
        for (int j = 0; j < 8; j++) u[j] = ffma2(v, sW1[k * 16 + jb + j], u[j]);
    }
#pragma unroll
    for (int j = 0; j < 8; j++) u[j] = relu2(u[j]);

    // ---- MLP2 layer2: 32 -> 8; partial over this lane's 16 input channels ----
    u64 a2[4];
#pragma unroll
    for (int j = 0; j < 4; j++) a2[j] = (q == 0) ? sB2[j] : pk2(0.f, 0.f);
#pragma unroll
    for (int kp = 0; kp < 8; kp++) {
        int c0 = 2 * (jb + kp);            // global input channel
        float va, vb; upk2(u[kp], va, vb);
        u64 pa = pk2(va, va), pb = pk2(vb, vb);
#pragma unroll
        for (int j = 0; j < 4; j++) a2[j] = ffma2(pa, sW2[c0 * 4 + j], a2[j]);
#pragma unroll
        for (int j = 0; j < 4; j++) a2[j] = ffma2(pb, sW2[(c0 + 1) * 4 + j], a2[j]);
    }
#pragma unroll
    for (int j = 0; j < 4; j++) a2[j] = add2(a2[j], shflx1_u64(a2[j]));

    float hn[HID];
#pragma unroll
    for (int j = 0; j < 4; j++) {
        float va, vb; upk2(a2[j], va, vb);
        hn[2 * j + 0] = tanhf_(fmaxf(va, 0.f));
        hn[2 * j + 1] = tanhf_(fmaxf(vb, 0.f));
    }

    // ---- Output head: 8 -> 16 -> 1; this lane's 4 pairs ----
    int ob4 = q * 4;
    u64 o[4];
#pragma unroll
    for (int j = 0; j < 4; j++) o[j] = sOB1[ob4 + j];
#pragma unroll
    for (int k = 0; k < 8; k++) {
        u64 v = pk2(hn[k], hn[k]);
#pragma unroll
        for (int j = 0; j < 4; j++) o[j] = ffma2(v, sO1[k * 8 + ob4 + j], o[j]);
    }
    u64 sp = pk2(0.f, 0.f);
#pragma unroll
    for (int j = 0; j < 4; j++) sp = ffma2(relu2(o[j]), sO2[ob4 + j], sp);
    float sa, sb; upk2(sp, sa, sb);
    float spart = sa + sb;
    float stot = spart + __shfl_xor_sync(0xFFFFFFFFu, spart, 1);
    if (valid && q == 0) {
        out[(size_t)t * N + n] = sigmoidf_(stot + sOB2);
        g_h[n * 2 + 0] = make_float4(hn[0], hn[1], hn[2], hn[3]);
        g_h[n * 2 + 1] = make_float4(hn[4], hn[5], hn[6], hn[7]);
    }

    // ---- MLP1 for next frame's v ----
    if (t + 1 < T_FRAMES) {
        float x0n = x[(size_t)nc * T_FRAMES * 2 + (size_t)(t + 1) * 2 + 0];
        float in9[9] = {x0n, hn[0], hn[1], hn[2], hn[3], hn[4], hn[5], hn[6], hn[7]};

        // layer1: this lane's 8 pairs
        u64 h[8];
#pragma unroll
        for (int j = 0; j < 8; j++) h[j] = eB1[jb + j];
#pragma unroll
        for (int k = 0; k < 9; k++) {
            u64 v = pk2(in9[k], in9[k]);
#pragma unroll
            for (int j = 0; j < 8; j++) h[j] = ffma2(v, eW1[k * 16 + jb + j], h[j]);
        }
#pragma unroll
        for (int j = 0; j < 8; j++) h[j] = relu2(h[j]);

        // exchange: partner's 8 pairs
        u64 hx[8];
#pragma unroll
        for (int j = 0; j < 8; j++) hx[j] = shflx1_u64(h[j]);

        // layer2: this lane's 8 output pairs over all 32 input channels
        int obp = 8 - jb;                  // partner's pair base
        u64 acc[8];
#pragma unroll
        for (int j = 0; j < 8; j++) acc[j] = eB2[jb + j];
#pragma unroll
        for (int kp = 0; kp < 8; kp++) {   // own channels
            int c0 = 2 * (jb + kp);
            float va, vb; upk2(h[kp], va, vb);
            u64 pa = pk2(va, va), pb = pk2(vb, vb);
#pragma unroll
            for (int j = 0; j < 8; j++) acc[j] = ffma2(pa, eW2[c0 * 16 + jb + j], acc[j]);
#pragma unroll
            for (int j = 0; j < 8; j++) acc[j] = ffma2(pb, eW2[(c0 + 1) * 16 + jb + j], acc[j]);
        }
#pragma unroll
        for (int kp = 0; kp < 8; kp++) {   // partner channels
            int c0 = 2 * (obp + kp);
            float va, vb; upk2(hx[kp], va, vb);
            u64 pa = pk2(va, va), pb = pk2(vb, vb);
#pragma unroll
            for (int j = 0; j < 8; j++) acc[j] = ffma2(pa, eW2[c0 * 16 + jb + j], acc[j]);
#pragma unroll
            for (int j = 0; j < 8; j++) acc[j] = ffma2(pb, eW2[(c0 + 1) * 16 + jb + j], acc[j]);
        }

        u64 vp = pk2(0.f, 0.f);
#pragma unroll
        for (int j = 0; j < 8; j++) vp = ffma2(relu2(acc[j]), eW3[jb + j], vp);
        float va, vb; upk2(vp, va, vb);
        float vpart = va + vb;
        float vtot = vpart + __shfl_xor_sync(0xFFFFFFFFu, vpart, 1);
        if (valid && q == 0) g_v[n] = sigmoidf_(vtot + eB3);
    }
}

// ---------------------------------------------------------------------------
extern "C" void kernel_launch(void* const* d_in, const int* in_sizes, int n_in,
                              void* d_out, int out_size)
{
    const float* x  = (const float*)d_in[0];
    const int*   ei = (const int*)  d_in[1];
    const float* ea = (const float*)d_in[2];

    EdgeW ew;
    ew.w1 = (const float*)d_in[3];  ew.b1 = (const float*)d_in[4];
    ew.w2 = (const float*)d_in[5];  ew.b2 = (const float*)d_in[6];
    ew.w3 = (const float*)d_in[7];  ew.b3 = (const float*)d_in[8];

    NodeW nw;
    nw.w1  = (const float*)d_in[9];  nw.b1  = (const float*)d_in[10];
    nw.w2  = (const float*)d_in[11]; nw.b2  = (const float*)d_in[12];
    nw.ow1 = (const float*)d_in[13]; nw.ob1 = (const float*)d_in[14];
    nw.ow2 = (const float*)d_in[15]; nw.ob2 = (const float*)d_in[16];

    float* out = (float*)d_out;

    int N = out_size / T_FRAMES;          // 50000
    int E = in_sizes[2] / T_FRAMES;       // 1000000

    int nb = (N + 255) / 256;
    int nb2 = (2 * N + 255) / 256;        // 2 threads per node
    int eb = ((E + 7) / 8 + 255) / 256;
    int tb = (E + 255) / 256;

    transpose_ea_kernel<<<tb, 256>>>(ea, E);
    init_kernel<<<nb, 256>>>(x, ew, N);
    for (int t = 0; t < T_FRAMES; t++) {
        edge_kernel<<<eb, 256>>>(ei, E, t);
        node_kernel<<<nb2, 256>>>(x, nw, ew, out, N, t);
    }
}